// round 7
// baseline (speedup 1.0000x reference)
#include <cuda_runtime.h>

// CapsuleLayer dynamic routing: 3 streaming passes (u_hat recomputed from W;
// b_ij == u_hat·(v0+..+v_{r-1})) + 3 squash kernels.
// R6 = R5 with hang-proof barriers: warp-specialized passes (8 compute warps +
// 2 W-staging warps, 320 thr) but ALL __syncthreads() in uniform control flow.
// v in padded shared (reg relief; launch_bounds caps regs -> no spills).

#define BB 32
#define JJ 32
#define II 4608
#define DA 8
#define DD 16
#define CHUNK 32
#define NCHUNK 144
#define OUTSZ (BB * JJ * DD)   // 16384
#define CAP_EPS 1e-7f
#define VSTRIDE 20             // padded v row: 5j mod 32 -> conflict-free LDS.128

typedef unsigned long long u64;

__device__ float g_partial[NCHUNK * OUTSZ]; // per-chunk partial s (9.4 MB)
__device__ float g_vsum[OUTSZ];             // v0, then v0+v1

__device__ __forceinline__ u64 pack2(float x, float y) {
    u64 r; asm("mov.b64 %0, {%1, %2};" : "=l"(r) : "f"(x), "f"(y)); return r;
}
__device__ __forceinline__ void unpack2(u64 v, float& x, float& y) {
    asm("mov.b64 {%0, %1}, %2;" : "=f"(x), "=f"(y) : "l"(v));
}
__device__ __forceinline__ u64 ffma2(u64 a, u64 b, u64 c) {
    u64 d; asm("fma.rn.f32x2 %0, %1, %2, %3;" : "=l"(d) : "l"(a), "l"(b), "l"(c)); return d;
}

// ---- W tile staging (staging warps only) -----------------------------------
// Tile for i = [32 j][128 z] floats (z = d*8+a in global). Stored transposed
// to [a][d] per j with float4-XOR swizzle: float z' = a*16+d at
//   phys = j*128 + ((z'>>2) ^ j)*4 + (z'&3)
// Staging thread st (0..63): row sj = st>>1, column half sfb = (st&1)*4.
__device__ __forceinline__ void stage_tile(float* slot, const float4* Wg4,
                                           int sj, int sfb, int ig) {
    float4 g[16];
#pragma unroll
    for (int m = 0; m < 16; m++) {
        int k2 = m >> 2, sf2 = sfb + (m & 3);
        g[m] = Wg4[(sj * II + ig) * 32 + k2 * 8 + sf2];
    }
    float* row = slot + sj * 128;
#pragma unroll
    for (int m = 0; m < 16; m++) {
        int k2 = m >> 2, sf2 = sfb + (m & 3);
        int ssub = sf2 >> 1, sq0 = (sf2 & 1) << 4;
        row[((sq0 + 0  + k2) ^ sj) * 4 + ssub] = g[m].x;
        row[((sq0 + 4  + k2) ^ sj) * 4 + ssub] = g[m].y;
        row[((sq0 + 8  + k2) ^ sj) * 4 + ssub] = g[m].z;
        row[((sq0 + 12 + k2) ^ sj) * 4 + ssub] = g[m].w;
    }
}

// ---------------------------------------------------------------------------
// Pass kernel: 144 CTAs (one 32-i chunk, all 32 batches), 320 threads.
// Warps 0..7 compute (lane = j; warp w owns batches 4w..4w+3);
// warps 8,9 stage W tiles (2-i windows, 4-slot ring).
// Dynamic shared (180224 B):
//   [0,16384)       W ring: 4 slots x 4096 floats (slot = il & 3)
//   [16384,24576)   x chunk: xsh[b*256 + il*8 + a]
//   [24576,45056)   v padded: vsh[(b*32+j)*VSTRIDE + d]   (PASS>0)
// ---------------------------------------------------------------------------
template <int PASS>
__global__ void __launch_bounds__(320, 1)
pass_kernel(const float* __restrict__ xg, const float* __restrict__ Wg) {
    extern __shared__ float sh[];
    float* xsh = sh + 16384;
    float* vsh = sh + 24576;
    const float4* Wg4 = (const float4*)Wg;
    const int t  = threadIdx.x;
    const int i0 = blockIdx.x * CHUNK;

    const bool is_compute = (t < 256);
    const int j  = t & 31;
    const int w  = t >> 5;
    const int b0 = (w & 7) * 4;
    const int st  = t & 63;          // staging id (valid when !is_compute)
    const int sj  = st >> 1;
    const int sfb = (st & 1) * 4;

    // v -> padded shared (all threads help)
    if (PASS > 0) {
        for (int e = t; e < OUTSZ; e += 320) {
            int bj = e >> 4;
            vsh[bj * VSTRIDE + (e & 15)] = g_vsum[e];
        }
    }
    // x chunk (contiguous 256 floats per b)
    for (int idx = t; idx < 8192; idx += 320) {
        int b = idx >> 8;
        xsh[idx] = xg[b * (II * DA) + i0 * DA + (idx & 255)];
    }
    // prologue: staging warps fill ring slots 0,1
    if (!is_compute) {
        stage_tile(sh,        Wg4, sj, sfb, i0 + 0);
        stage_tile(sh + 4096, Wg4, sj, sfb, i0 + 1);
    }

    u64 acc2[4][DD / 2];
#pragma unroll
    for (int bi = 0; bi < 4; bi++)
#pragma unroll
        for (int dp = 0; dp < DD / 2; dp++) acc2[bi][dp] = 0ull;

    auto compute = [&](int il) {
        const ulonglong2* wb =
            (const ulonglong2*)(sh + ((il & 3) << 12) + j * 128);
        const float* xb = xsh + il * 8;

        u64 u2[4][DD / 2];
        if (PASS > 0) {
#pragma unroll
            for (int bi = 0; bi < 4; bi++)
#pragma unroll
                for (int dp = 0; dp < DD / 2; dp++) u2[bi][dp] = 0ull;
        }

#pragma unroll
        for (int a = 0; a < DA; a++) {
            u64 xx[4];
#pragma unroll
            for (int bi = 0; bi < 4; bi++) {
                float xv = xb[(b0 + bi) * 256 + a];      // broadcast LDS
                xx[bi] = pack2(xv, xv);
            }
#pragma unroll
            for (int d4 = 0; d4 < 4; d4++) {
                ulonglong2 wv = wb[((a << 2) | d4) ^ j]; // conflict-free LDS.128
#pragma unroll
                for (int bi = 0; bi < 4; bi++) {
                    if (PASS == 0) {                     // uniform c folded later
                        acc2[bi][2 * d4]     = ffma2(wv.x, xx[bi], acc2[bi][2 * d4]);
                        acc2[bi][2 * d4 + 1] = ffma2(wv.y, xx[bi], acc2[bi][2 * d4 + 1]);
                    } else {
                        u2[bi][2 * d4]     = ffma2(wv.x, xx[bi], u2[bi][2 * d4]);
                        u2[bi][2 * d4 + 1] = ffma2(wv.y, xx[bi], u2[bi][2 * d4 + 1]);
                    }
                }
            }
        }

        if (PASS > 0) {
#pragma unroll
            for (int bi = 0; bi < 4; bi++) {
                const ulonglong2* vp =
                    (const ulonglong2*)(vsh + ((b0 + bi) * JJ + j) * VSTRIDE);
                u64 lp = 0ull;
#pragma unroll
                for (int k = 0; k < 4; k++) {
                    ulonglong2 vv = vp[k];
                    lp = ffma2(u2[bi][2 * k],     vv.x, lp);
                    lp = ffma2(u2[bi][2 * k + 1], vv.y, lp);
                }
                float lo, hi; unpack2(lp, lo, hi);
                // softmax over j = lanes (logits bounded -> skip max-subtract)
                float e = __expf(lo + hi);
                float z = e;
#pragma unroll
                for (int off = 16; off > 0; off >>= 1)
                    z += __shfl_xor_sync(0xffffffffu, z, off);
                float c = __fdividef(e, z);
                u64 cc = pack2(c, c);
#pragma unroll
                for (int dp = 0; dp < DD / 2; dp++)
                    acc2[bi][dp] = ffma2(cc, u2[bi][dp], acc2[bi][dp]);
            }
        }
    };

    __syncthreads();  // B0 (uniform): tiles 0,1 + x + v visible to all

    // main loop: barrier at window boundary, uniform for all 320 threads
    for (int pp = 0; pp < CHUNK / 2; ++pp) {
        if (is_compute) {
            compute(2 * pp);
            compute(2 * pp + 1);
        } else if (pp + 1 < CHUNK / 2) {
            int T = 2 * pp + 2;
            // slot T&3 last read in window pp-1 (tile T-4) -> safe to overwrite
            stage_tile(sh + ((T & 3) << 12),       Wg4, sj, sfb, i0 + T);
            stage_tile(sh + (((T + 1) & 3) << 12), Wg4, sj, sfb, i0 + T + 1);
        }
        if (pp + 1 < CHUNK / 2) __syncthreads();  // uniform
    }

    // per-chunk partials (deterministic two-stage reduction)
    if (is_compute) {
#pragma unroll
        for (int bi = 0; bi < 4; bi++) {
            u64* p = (u64*)&g_partial[((blockIdx.x * BB + (b0 + bi)) * JJ + j) * DD];
#pragma unroll
            for (int dp = 0; dp < DD / 2; dp++) p[dp] = acc2[bi][dp];
        }
    }
}

// ---------------------------------------------------------------------------
// Squash: 128 CTAs x 1024 threads. Output o handled by 8 threads (18 chunks
// each, 3-way ILP), combined in shared; 16-lane shfl for |s|^2.
// ---------------------------------------------------------------------------
template <int ROUND>
__global__ void __launch_bounds__(1024)
squash_kernel(float* __restrict__ out) {
    __shared__ float red[1024];
    const int tt = threadIdx.x & 127;
    const int o  = (int)blockIdx.x * 128 + tt;  // (b*JJ+j)*DD + d
    const int q  = threadIdx.x >> 7;            // chunk slice 0..7

    const float* p = g_partial + q * 18 * OUTSZ + o;
    float s0 = 0.f, s1 = 0.f, s2 = 0.f;
#pragma unroll
    for (int c = 0; c < 18; c += 3) {
        s0 += p[(c + 0) * OUTSZ];
        s1 += p[(c + 1) * OUTSZ];
        s2 += p[(c + 2) * OUTSZ];
    }
    red[threadIdx.x] = (s0 + s1) + s2;
    __syncthreads();

    if (q == 0) {
        float s = ((red[tt] + red[tt + 128]) + (red[tt + 256] + red[tt + 384]))
                + ((red[tt + 512] + red[tt + 640]) + (red[tt + 768] + red[tt + 896]));
        if (ROUND == 0) s *= 0.03125f;  // uniform c = 1/32 folded here

        float sq = s * s;  // d-groups of 16 aligned within the warp
#pragma unroll
        for (int off = 8; off > 0; off >>= 1)
            sq += __shfl_xor_sync(0xffffffffu, sq, off);

        float v = s * (sq / ((1.0f + sq) * sqrtf(sq + CAP_EPS)));

        if (ROUND == 0)      g_vsum[o] = v;
        else if (ROUND == 1) g_vsum[o] += v;
        else                 out[o] = v;
    }
}

// ---------------------------------------------------------------------------
extern "C" void kernel_launch(void* const* d_in, const int* in_sizes, int n_in,
                              void* d_out, int out_size) {
    (void)in_sizes; (void)n_in; (void)out_size;
    const float* xg = (const float*)d_in[0];   // inputs [32,4608,8]
    const float* Wg = (const float*)d_in[1];   // W      [32,4608,16,8]
    float* out = (float*)d_out;                // [32,32,16]

    const int SMEM = 45056 * 4;  // 176 KB dynamic
    cudaFuncSetAttribute(pass_kernel<0>, cudaFuncAttributeMaxDynamicSharedMemorySize, SMEM);
    cudaFuncSetAttribute(pass_kernel<1>, cudaFuncAttributeMaxDynamicSharedMemorySize, SMEM);
    cudaFuncSetAttribute(pass_kernel<2>, cudaFuncAttributeMaxDynamicSharedMemorySize, SMEM);

    pass_kernel<0><<<NCHUNK, 320, SMEM>>>(xg, Wg);
    squash_kernel<0><<<128, 1024>>>(out);
    pass_kernel<1><<<NCHUNK, 320, SMEM>>>(xg, Wg);
    squash_kernel<1><<<128, 1024>>>(out);
    pass_kernel<2><<<NCHUNK, 320, SMEM>>>(xg, Wg);
    squash_kernel<2><<<128, 1024>>>(out);
}

// round 8
// speedup vs baseline: 1.0639x; 1.0639x over previous
#include <cuda_runtime.h>

// CapsuleLayer dynamic routing: 3 streaming passes (u_hat recomputed from W;
// b_ij == u_hat·(v0+..+v_{r-1})) + 3 squash kernels.
// R7: lane = BATCH (not j). 16 warps x 2 j's. All W shared reads are
// lane-uniform -> broadcast (crossbar ~free). Softmax over j becomes a
// cross-warp exchange with exactly one uniform __syncthreads per i.

#define BB 32
#define JJ 32
#define II 4608
#define DA 8
#define DD 16
#define CHUNK 32
#define NCHUNK 144
#define OUTSZ (BB * JJ * DD)   // 16384
#define CAP_EPS 1e-7f

// shared memory float offsets
#define RING 0        // W ring: 4 slots x 4096 floats (64 KB)
#define XT   16384    // x transposed: [il*8+a][b]          (8192 floats)
#define VT   24576    // v transposed: float2 [(j*8+dp)][b] (16384 floats)
#define PB   40960    // softmax partials: 2 x [b*20 + w]   (1280 floats)
#define SMEM_FLOATS 42240

typedef unsigned long long u64;

__device__ float g_partial[NCHUNK * OUTSZ]; // per-chunk partial s (9.4 MB)
__device__ float g_vsum[OUTSZ];             // v0, then v0+v1

__device__ __forceinline__ u64 pack2(float x, float y) {
    u64 r; asm("mov.b64 %0, {%1, %2};" : "=l"(r) : "f"(x), "f"(y)); return r;
}
__device__ __forceinline__ void unpack2(u64 v, float& x, float& y) {
    asm("mov.b64 {%0, %1}, %2;" : "=f"(x), "=f"(y) : "l"(v));
}
__device__ __forceinline__ u64 ffma2(u64 a, u64 b, u64 c) {
    u64 d; asm("fma.rn.f32x2 %0, %1, %2, %3;" : "=l"(d) : "l"(a), "l"(b), "l"(c)); return d;
}

// ---- W tile store: transpose [d][a] -> [a][d] with float4-XOR swizzle ------
// Global float4 f (0..31) of row holds d = f>>1, a = 4*(f&1)+c (c = component).
// Target float z' = a*16+d at  phys = row + ((z'>>2) ^ sj)*4 + (z'&3).
__device__ __forceinline__ void stw(float* row, float4 v, int f, int sj) {
    const int base = 16 * (f & 1) + (f >> 3);
    const int lo   = (f >> 1) & 3;
    row[(((base + 0 ) ^ sj) << 2) + lo] = v.x;
    row[(((base + 4 ) ^ sj) << 2) + lo] = v.y;
    row[(((base + 8 ) ^ sj) << 2) + lo] = v.z;
    row[(((base + 12) ^ sj) << 2) + lo] = v.w;
}

// ---------------------------------------------------------------------------
// Pass kernel: 144 CTAs (one 32-i chunk, all 32 batches), 512 threads.
// lane = b; warp w (0..15) owns j = 2w, 2w+1. One uniform barrier per i.
// ---------------------------------------------------------------------------
template <int PASS>
__global__ void __launch_bounds__(512, 1)
pass_kernel(const float* __restrict__ xg, const float* __restrict__ Wg) {
    extern __shared__ float sh[];
    const float4* Wg4 = (const float4*)Wg;
    const int t  = threadIdx.x;
    const int b  = t & 31;          // lane = batch
    const int w  = t >> 5;          // warp 0..15
    const int j0 = 2 * w;           // this warp's two output capsules
    const int i0 = blockIdx.x * CHUNK;
    const int sj = t >> 4;          // staging row 0..31
    const int q  = t & 15;          // staging float4 sub-index

    // ---- x transpose: xg[b,i0+il,a] -> XT[(il*8+a)*32 + b] ----
#pragma unroll
    for (int k = 0; k < 16; k++) {
        int e = t + k * 512;
        int bb = e >> 8, rem = e & 255;
        sh[XT + rem * 32 + bb] = xg[bb * (II * DA) + i0 * DA + rem];
    }
    // ---- v transpose (PASS>0): g_vsum[(b*32+j)*16+d] -> VT float2[(j*8+dp)][b]
    if (PASS > 0) {
#pragma unroll
        for (int k = 0; k < 32; k++) {
            int e = t + k * 512;
            int d = e & 15, jj = (e >> 4) & 31, bb = e >> 9;
            sh[VT + ((jj * 8 + (d >> 1)) * 32 + bb) * 2 + (d & 1)] = g_vsum[e];
        }
    }
    // ---- W prologue: tiles 0,1 staged; tile 2 prefetched into g ----
    float4 g0, g1;
    g0 = Wg4[(sj * II + i0 + 0) * 32 + q];
    g1 = Wg4[(sj * II + i0 + 0) * 32 + q + 16];
    stw(sh + RING + sj * 128, g0, q, sj);
    stw(sh + RING + sj * 128, g1, q + 16, sj);
    g0 = Wg4[(sj * II + i0 + 1) * 32 + q];
    g1 = Wg4[(sj * II + i0 + 1) * 32 + q + 16];
    stw(sh + RING + 4096 + sj * 128, g0, q, sj);
    stw(sh + RING + 4096 + sj * 128, g1, q + 16, sj);
    g0 = Wg4[(sj * II + i0 + 2) * 32 + q];
    g1 = Wg4[(sj * II + i0 + 2) * 32 + q + 16];
    __syncthreads();

    u64 acc2[2][DD / 2];
#pragma unroll
    for (int jj = 0; jj < 2; jj++)
#pragma unroll
        for (int dp = 0; dp < DD / 2; dp++) acc2[jj][dp] = 0ull;

    float ev0 = 0.f, ev1 = 0.f;

    for (int il = 0; il < CHUNK; ++il) {
        // ---- stage: store tile il+2 (slot last read at il-2, barrier since),
        //      prefetch tile il+3 into registers ----
        if (il + 2 < CHUNK) {
            float* row = sh + RING + (((il + 2) & 3) << 12) + sj * 128;
            stw(row, g0, q, sj);
            stw(row, g1, q + 16, sj);
            if (il + 3 < CHUNK) {
                g0 = Wg4[(sj * II + i0 + il + 3) * 32 + q];
                g1 = Wg4[(sj * II + i0 + il + 3) * 32 + q + 16];
            }
        }

        // ---- x for this (b, il): 8 scalars, conflict-free, packed ----
        u64 xx[DA];
#pragma unroll
        for (int a = 0; a < DA; a++) {
            float xv = sh[XT + (il * 8 + a) * 32 + b];
            xx[a] = pack2(xv, xv);
        }

        // ---- u_hat for j0, j0+1: all W reads lane-uniform (broadcast) ----
        u64 u2[2][DD / 2];
#pragma unroll
        for (int jj = 0; jj < 2; jj++)
#pragma unroll
            for (int dp = 0; dp < DD / 2; dp++) u2[jj][dp] = 0ull;

#pragma unroll
        for (int jj = 0; jj < 2; jj++) {
            const int j = j0 + jj;
            const ulonglong2* wbj =
                (const ulonglong2*)(sh + RING + ((il & 3) << 12)) + j * 32;
#pragma unroll
            for (int a = 0; a < DA; a++) {
#pragma unroll
                for (int d4 = 0; d4 < 4; d4++) {
                    ulonglong2 wv = wbj[((a << 2) | d4) ^ j];   // broadcast
                    if (PASS == 0) {   // uniform c folded into squash round 0
                        acc2[jj][2 * d4]     = ffma2(wv.x, xx[a], acc2[jj][2 * d4]);
                        acc2[jj][2 * d4 + 1] = ffma2(wv.y, xx[a], acc2[jj][2 * d4 + 1]);
                    } else {
                        u2[jj][2 * d4]     = ffma2(wv.x, xx[a], u2[jj][2 * d4]);
                        u2[jj][2 * d4 + 1] = ffma2(wv.y, xx[a], u2[jj][2 * d4 + 1]);
                    }
                }
            }
        }

        // ---- logits + per-warp exp partial (PASS>0) ----
        if (PASS > 0) {
#pragma unroll
            for (int jj = 0; jj < 2; jj++) {
                const int j = j0 + jj;
                u64 lp = 0ull;
#pragma unroll
                for (int dp = 0; dp < DD / 2; dp++) {
                    u64 vv = *(const u64*)(sh + VT + ((j * 8 + dp) * 32 + b) * 2);
                    lp = ffma2(u2[jj][dp], vv, lp);
                }
                float lo, hi; unpack2(lp, lo, hi);
                // logits bounded (|u|,|v| small) -> skip max-subtract
                float e = __expf(lo + hi);
                if (jj == 0) ev0 = e; else ev1 = e;
            }
            sh[PB + (il & 1) * 640 + b * 20 + w] = ev0 + ev1;
        }

        __syncthreads();   // uniform: publishes partials AND staging for il+1

        // ---- finish softmax over all 32 j, weighted accumulate ----
        if (PASS > 0) {
            const float4* pz = (const float4*)(sh + PB + (il & 1) * 640 + b * 20);
            float4 z0 = pz[0], z1 = pz[1], z2 = pz[2], z3 = pz[3];
            float Z = ((z0.x + z0.y) + (z0.z + z0.w))
                    + ((z1.x + z1.y) + (z1.z + z1.w))
                    + ((z2.x + z2.y) + (z2.z + z2.w))
                    + ((z3.x + z3.y) + (z3.z + z3.w));
            float c0 = __fdividef(ev0, Z);
            float c1 = __fdividef(ev1, Z);
            u64 cc0 = pack2(c0, c0), cc1 = pack2(c1, c1);
#pragma unroll
            for (int dp = 0; dp < DD / 2; dp++) {
                acc2[0][dp] = ffma2(cc0, u2[0][dp], acc2[0][dp]);
                acc2[1][dp] = ffma2(cc1, u2[1][dp], acc2[1][dp]);
            }
        }
    }

    // ---- per-chunk partials (deterministic two-stage reduction) ----
#pragma unroll
    for (int jj = 0; jj < 2; jj++) {
        u64* p = (u64*)&g_partial[((blockIdx.x * BB + b) * JJ + (j0 + jj)) * DD];
#pragma unroll
        for (int dp = 0; dp < DD / 2; dp++) p[dp] = acc2[jj][dp];
    }
}

// ---------------------------------------------------------------------------
// Squash: 128 CTAs x 1024 threads. Output o handled by 8 threads (18 chunks
// each, 3-way ILP), combined in shared; 16-lane shfl for |s|^2.
// ---------------------------------------------------------------------------
template <int ROUND>
__global__ void __launch_bounds__(1024)
squash_kernel(float* __restrict__ out) {
    __shared__ float red[1024];
    const int tt = threadIdx.x & 127;
    const int o  = (int)blockIdx.x * 128 + tt;  // (b*JJ+j)*DD + d
    const int qq = threadIdx.x >> 7;            // chunk slice 0..7

    const float* p = g_partial + qq * 18 * OUTSZ + o;
    float s0 = 0.f, s1 = 0.f, s2 = 0.f;
#pragma unroll
    for (int c = 0; c < 18; c += 3) {
        s0 += p[(c + 0) * OUTSZ];
        s1 += p[(c + 1) * OUTSZ];
        s2 += p[(c + 2) * OUTSZ];
    }
    red[threadIdx.x] = (s0 + s1) + s2;
    __syncthreads();

    if (qq == 0) {
        float s = ((red[tt] + red[tt + 128]) + (red[tt + 256] + red[tt + 384]))
                + ((red[tt + 512] + red[tt + 640]) + (red[tt + 768] + red[tt + 896]));
        if (ROUND == 0) s *= 0.03125f;  // uniform c = 1/32 folded here

        float sq = s * s;  // d-groups of 16 aligned within the warp
#pragma unroll
        for (int off = 8; off > 0; off >>= 1)
            sq += __shfl_xor_sync(0xffffffffu, sq, off);

        float v = s * (sq / ((1.0f + sq) * sqrtf(sq + CAP_EPS)));

        if (ROUND == 0)      g_vsum[o] = v;
        else if (ROUND == 1) g_vsum[o] += v;
        else                 out[o] = v;
    }
}

// ---------------------------------------------------------------------------
extern "C" void kernel_launch(void* const* d_in, const int* in_sizes, int n_in,
                              void* d_out, int out_size) {
    (void)in_sizes; (void)n_in; (void)out_size;
    const float* xg = (const float*)d_in[0];   // inputs [32,4608,8]
    const float* Wg = (const float*)d_in[1];   // W      [32,4608,16,8]
    float* out = (float*)d_out;                // [32,32,16]

    const int SMEM = SMEM_FLOATS * 4;  // 168960 B dynamic
    cudaFuncSetAttribute(pass_kernel<0>, cudaFuncAttributeMaxDynamicSharedMemorySize, SMEM);
    cudaFuncSetAttribute(pass_kernel<1>, cudaFuncAttributeMaxDynamicSharedMemorySize, SMEM);
    cudaFuncSetAttribute(pass_kernel<2>, cudaFuncAttributeMaxDynamicSharedMemorySize, SMEM);

    pass_kernel<0><<<NCHUNK, 512, SMEM>>>(xg, Wg);
    squash_kernel<0><<<128, 1024>>>(out);
    pass_kernel<1><<<NCHUNK, 512, SMEM>>>(xg, Wg);
    squash_kernel<1><<<128, 1024>>>(out);
    pass_kernel<2><<<NCHUNK, 512, SMEM>>>(xg, Wg);
    squash_kernel<2><<<128, 1024>>>(out);
}

// round 10
// speedup vs baseline: 1.4825x; 1.3934x over previous
#include <cuda_runtime.h>

// CapsuleLayer dynamic routing: 3 streaming passes (u_hat recomputed from W;
// b_ij == u_hat·(v0+..+v_{r-1})) + 3 squash kernels.
// R9 = R8 resubmitted (container infra flake, kernel audited clean):
// R3 pass structure (256 thr, lane=j, 4 batches/warp, inline 4-slot W ring,
// barrier per 2 i) + v in padded shared (frees 64 regs -> no spills)
// + high-occupancy squash.

#define BB 32
#define JJ 32
#define II 4608
#define DA 8
#define DD 16
#define CHUNK 32
#define NCHUNK 144
#define OUTSZ (BB * JJ * DD)   // 16384
#define CAP_EPS 1e-7f
#define VSTRIDE 20             // padded v row: 5j mod 8 quads -> conflict-free

typedef unsigned long long u64;

__device__ float g_partial[NCHUNK * OUTSZ]; // per-chunk partial s (9.4 MB)
__device__ float g_vsum[OUTSZ];             // v0, then v0+v1

__device__ __forceinline__ u64 pack2(float x, float y) {
    u64 r; asm("mov.b64 %0, {%1, %2};" : "=l"(r) : "f"(x), "f"(y)); return r;
}
__device__ __forceinline__ void unpack2(u64 v, float& x, float& y) {
    asm("mov.b64 {%0, %1}, %2;" : "=f"(x), "=f"(y) : "l"(v));
}
__device__ __forceinline__ u64 ffma2(u64 a, u64 b, u64 c) {
    u64 d; asm("fma.rn.f32x2 %0, %1, %2, %3;" : "=l"(d) : "l"(a), "l"(b), "l"(c)); return d;
}

// W tile staging: tile for i is [32 j][128 z] floats (z = d*8+a in global),
// stored transposed to [a][d] per j with float4-XOR swizzle:
// float z' = a*16+d at  phys = j*128 + ((z'>>2) ^ j)*4 + (z'&3).
__device__ __forceinline__ void stage_load(float4* g, const float4* Wg4,
                                           int sj, int sf, int ig) {
#pragma unroll
    for (int k = 0; k < 4; k++) g[k] = Wg4[(sj * II + ig) * 32 + k * 8 + sf];
}
__device__ __forceinline__ void stage_store(float* slot, const float4* g,
                                            int sj, int sq0, int ssub) {
    float* row = slot + sj * 128;
#pragma unroll
    for (int k = 0; k < 4; k++) {
        row[((sq0 + 0  + k) ^ sj) * 4 + ssub] = g[k].x;
        row[((sq0 + 4  + k) ^ sj) * 4 + ssub] = g[k].y;
        row[((sq0 + 8  + k) ^ sj) * 4 + ssub] = g[k].z;
        row[((sq0 + 12 + k) ^ sj) * 4 + ssub] = g[k].w;
    }
}

// ---------------------------------------------------------------------------
// Pass kernel: 144 CTAs (one 32-i chunk, all 32 batches), 256 threads = 8 warps.
// lane = j; warp w owns batches 4w..4w+3.
// Dynamic shared (180224 B):
//   [0,16384)       W ring: 4 slots x 4096 floats (slot = il & 3)
//   [16384,24576)   x chunk: xsh[b*256 + il*8 + a]
//   [24576,45056)   v padded: vsh[(b*32+j)*VSTRIDE + d]   (PASS>0)
// ---------------------------------------------------------------------------
template <int PASS>
__global__ void __launch_bounds__(256, 1)
pass_kernel(const float* __restrict__ xg, const float* __restrict__ Wg) {
    extern __shared__ float sh[];
    float* xsh = sh + 16384;
    float* vsh = sh + 24576;
    const float4* Wg4 = (const float4*)Wg;

    const int t  = threadIdx.x;
    const int j  = t & 31;         // lane = output capsule
    const int w  = t >> 5;         // warp 0..7
    const int b0 = w * 4;
    const int i0 = blockIdx.x * CHUNK;
    const int sj   = t >> 3;       // staging row 0..31
    const int sf   = t & 7;
    const int ssub = sf >> 1;
    const int sq0  = (sf & 1) << 4;

    // v -> padded shared (replaces the 64-reg v cache of R3/R4)
    if (PASS > 0) {
        for (int e = t; e < OUTSZ; e += 256) {
            int bj = e >> 4;
            vsh[bj * VSTRIDE + (e & 15)] = g_vsum[e];
        }
    }
    // x: full chunk, contiguous 256 floats per b
    for (int idx = t; idx < 8192; idx += 256) {
        int b = idx >> 8;
        xsh[idx] = xg[b * (II * DA) + i0 * DA + (idx & 255)];
    }

    // prologue: fill slots 0,1; prefetch i0+2 into regs
    float4 g[4];
    stage_load(g, Wg4, sj, sf, i0 + 0);
    stage_store(sh, g, sj, sq0, ssub);
    stage_load(g, Wg4, sj, sf, i0 + 1);
    stage_store(sh + 4096, g, sj, sq0, ssub);
    stage_load(g, Wg4, sj, sf, i0 + 2);
    __syncthreads();

    u64 acc2[4][DD / 2];
#pragma unroll
    for (int bi = 0; bi < 4; bi++)
#pragma unroll
        for (int dp = 0; dp < DD / 2; dp++) acc2[bi][dp] = 0ull;

    auto compute = [&](int il) {
        const ulonglong2* wb = (const ulonglong2*)(sh + ((il & 3) << 12) + j * 128);
        const float* xb = xsh + il * 8;

        u64 u2[4][DD / 2];
        if (PASS > 0) {
#pragma unroll
            for (int bi = 0; bi < 4; bi++)
#pragma unroll
                for (int dp = 0; dp < DD / 2; dp++) u2[bi][dp] = 0ull;
        }

#pragma unroll
        for (int a = 0; a < DA; a++) {
            u64 xx[4];
#pragma unroll
            for (int bi = 0; bi < 4; bi++) {
                float xv = xb[(b0 + bi) * 256 + a];      // broadcast LDS
                xx[bi] = pack2(xv, xv);
            }
#pragma unroll
            for (int d4 = 0; d4 < 4; d4++) {
                ulonglong2 wv = wb[((a << 2) | d4) ^ j]; // conflict-free LDS.128
#pragma unroll
                for (int bi = 0; bi < 4; bi++) {
                    if (PASS == 0) {                     // uniform c folded later
                        acc2[bi][2 * d4]     = ffma2(wv.x, xx[bi], acc2[bi][2 * d4]);
                        acc2[bi][2 * d4 + 1] = ffma2(wv.y, xx[bi], acc2[bi][2 * d4 + 1]);
                    } else {
                        u2[bi][2 * d4]     = ffma2(wv.x, xx[bi], u2[bi][2 * d4]);
                        u2[bi][2 * d4 + 1] = ffma2(wv.y, xx[bi], u2[bi][2 * d4 + 1]);
                    }
                }
            }
        }

        if (PASS > 0) {
#pragma unroll
            for (int bi = 0; bi < 4; bi++) {
                // v from padded shared: 4 LDS.128, conflict-free (5j mod 8 quads)
                const ulonglong2* vp =
                    (const ulonglong2*)(vsh + ((b0 + bi) * JJ + j) * VSTRIDE);
                u64 lp = 0ull;
#pragma unroll
                for (int k = 0; k < 4; k++) {
                    ulonglong2 vv = vp[k];
                    lp = ffma2(u2[bi][2 * k],     vv.x, lp);
                    lp = ffma2(u2[bi][2 * k + 1], vv.y, lp);
                }
                float lo, hi; unpack2(lp, lo, hi);
                // softmax over j = lanes (logits bounded -> skip max-subtract)
                float e = __expf(lo + hi);
                float z = e;
#pragma unroll
                for (int off = 16; off > 0; off >>= 1)
                    z += __shfl_xor_sync(0xffffffffu, z, off);
                float c = __fdividef(e, z);
                u64 cc = pack2(c, c);
#pragma unroll
                for (int dp = 0; dp < DD / 2; dp++)
                    acc2[bi][dp] = ffma2(cc, u2[bi][dp], acc2[bi][dp]);
            }
        }
    };

    for (int pp = 0; pp < CHUNK / 2; ++pp) {
        const int il0 = 2 * pp;
        compute(il0);
        if (pp + 1 < CHUNK / 2) {
            // slot (il0+2)&3 last read at il0-2 (before previous barrier) -> safe
            stage_store(sh + (((il0 + 2) & 3) << 12), g, sj, sq0, ssub);
            stage_load(g, Wg4, sj, sf, i0 + il0 + 3);
        }
        compute(il0 + 1);
        if (pp + 1 < CHUNK / 2) {
            stage_store(sh + (((il0 + 3) & 3) << 12), g, sj, sq0, ssub);
            if (pp + 2 < CHUNK / 2)
                stage_load(g, Wg4, sj, sf, i0 + il0 + 4);
            __syncthreads();
        }
    }

    // per-chunk partials (deterministic two-stage reduction)
#pragma unroll
    for (int bi = 0; bi < 4; bi++) {
        u64* p = (u64*)&g_partial[((blockIdx.x * BB + (b0 + bi)) * JJ + j) * DD];
#pragma unroll
        for (int dp = 0; dp < DD / 2; dp++) p[dp] = acc2[bi][dp];
    }
}

// ---------------------------------------------------------------------------
// Squash: 128 CTAs x 1024 threads. Output o handled by 8 threads (18 chunks
// each, 3-way ILP), combined in shared; 16-lane shfl for |s|^2.
// ---------------------------------------------------------------------------
template <int ROUND>
__global__ void __launch_bounds__(1024)
squash_kernel(float* __restrict__ out) {
    __shared__ float red[1024];
    const int tt = threadIdx.x & 127;
    const int o  = (int)blockIdx.x * 128 + tt;  // (b*JJ+j)*DD + d
    const int qq = threadIdx.x >> 7;            // chunk slice 0..7

    const float* p = g_partial + qq * 18 * OUTSZ + o;
    float s0 = 0.f, s1 = 0.f, s2 = 0.f;
#pragma unroll
    for (int c = 0; c < 18; c += 3) {
        s0 += p[(c + 0) * OUTSZ];
        s1 += p[(c + 1) * OUTSZ];
        s2 += p[(c + 2) * OUTSZ];
    }
    red[threadIdx.x] = (s0 + s1) + s2;
    __syncthreads();

    if (qq == 0) {
        float s = ((red[tt] + red[tt + 128]) + (red[tt + 256] + red[tt + 384]))
                + ((red[tt + 512] + red[tt + 640]) + (red[tt + 768] + red[tt + 896]));
        if (ROUND == 0) s *= 0.03125f;  // uniform c = 1/32 folded here

        float sq = s * s;  // d-groups of 16 aligned within the warp
#pragma unroll
        for (int off = 8; off > 0; off >>= 1)
            sq += __shfl_xor_sync(0xffffffffu, sq, off);

        float v = s * (sq / ((1.0f + sq) * sqrtf(sq + CAP_EPS)));

        if (ROUND == 0)      g_vsum[o] = v;
        else if (ROUND == 1) g_vsum[o] += v;
        else                 out[o] = v;
    }
}

// ---------------------------------------------------------------------------
extern "C" void kernel_launch(void* const* d_in, const int* in_sizes, int n_in,
                              void* d_out, int out_size) {
    (void)in_sizes; (void)n_in; (void)out_size;
    const float* xg = (const float*)d_in[0];   // inputs [32,4608,8]
    const float* Wg = (const float*)d_in[1];   // W      [32,4608,16,8]
    float* out = (float*)d_out;                // [32,32,16]

    const int SMEM = 45056 * 4;  // 176 KB dynamic
    cudaFuncSetAttribute(pass_kernel<0>, cudaFuncAttributeMaxDynamicSharedMemorySize, SMEM);
    cudaFuncSetAttribute(pass_kernel<1>, cudaFuncAttributeMaxDynamicSharedMemorySize, SMEM);
    cudaFuncSetAttribute(pass_kernel<2>, cudaFuncAttributeMaxDynamicSharedMemorySize, SMEM);

    pass_kernel<0><<<NCHUNK, 256, SMEM>>>(xg, Wg);
    squash_kernel<0><<<128, 1024>>>(out);
    pass_kernel<1><<<NCHUNK, 256, SMEM>>>(xg, Wg);
    squash_kernel<1><<<128, 1024>>>(out);
    pass_kernel<2><<<NCHUNK, 256, SMEM>>>(xg, Wg);
    squash_kernel<2><<<128, 1024>>>(out);
}